// round 1
// baseline (speedup 1.0000x reference)
#include <cuda_runtime.h>
#include <cuda_bf16.h>
#include <cstdint>

// ---------------------------------------------------------------------------
// LinearMPC: u <- clip(u - 0.01*(u@H^T + f)), 100 iters, B=2048, M=512.
// H symmetric => u@H^T = u@H (row-contiguous reduction).
// Persistent kernel: each CTA owns 16 batch rows, u resident in SMEM+regs,
// H streamed from L2 via double-buffered cp.async, math in packed f32x2 FMA.
// ---------------------------------------------------------------------------

#define NXD 8
#define NHOR 64
#define MD 512          // condensed dim
#define BATCH 2048
#define BT 16           // batch tile per CTA
#define NCH 8           // n-rows of H per chunk
#define NCHUNK (MD / NCH)
#define ITERS 100
#define STEPC 0.01f
#define THREADS 256

__device__ float g_f[BATCH * MD];   // linear term, computed by prologue kernel

// ---- packed f32x2 helpers (Blackwell FFMA2) -------------------------------
__device__ __forceinline__ unsigned long long pack2(float lo, float hi) {
    unsigned long long r;
    asm("mov.b64 %0, {%1, %2};" : "=l"(r) : "f"(lo), "f"(hi));
    return r;
}
__device__ __forceinline__ void unpack2(unsigned long long v, float& lo, float& hi) {
    asm("mov.b64 {%0, %1}, %2;" : "=f"(lo), "=f"(hi) : "l"(v));
}
__device__ __forceinline__ void fma2(unsigned long long& d,
                                     unsigned long long a,
                                     unsigned long long b) {
    asm("fma.rn.f32x2 %0, %1, %2, %0;" : "+l"(d) : "l"(a), "l"(b));
}

// ---- cp.async helpers -----------------------------------------------------
__device__ __forceinline__ void cp_async16(void* smem, const void* gmem) {
    unsigned saddr = (unsigned)__cvta_generic_to_shared(smem);
    asm volatile("cp.async.cg.shared.global [%0], [%1], 16;" :: "r"(saddr), "l"(gmem));
}
__device__ __forceinline__ void cp_commit() {
    asm volatile("cp.async.commit_group;");
}
template <int N>
__device__ __forceinline__ void cp_wait() {
    asm volatile("cp.async.wait_group %0;" :: "n"(N));
}

// ---------------------------------------------------------------------------
// Prologue: f[b, k*8+i] = -2 * sum_j Phi[k,i,j] * (sum_l Q[j,l]*dx[b,k,l])
//           dx[b,k,l] = xref[b,k,l] - xref[b,0,l]
// ---------------------------------------------------------------------------
__global__ void mpc_f_kernel(const float* __restrict__ xref,
                             const float* __restrict__ Phi,
                             const float* __restrict__ Q) {
    int b = blockIdx.x;
    int k = threadIdx.x;            // 0..63
    const float* xr = xref + (size_t)b * (NHOR + 1) * NXD;

    float dx[NXD];
#pragma unroll
    for (int l = 0; l < NXD; l++)
        dx[l] = xr[k * NXD + l] - xr[l];

    float t[NXD];
#pragma unroll
    for (int j = 0; j < NXD; j++) {
        float s = 0.f;
#pragma unroll
        for (int l = 0; l < NXD; l++)
            s = fmaf(Q[j * NXD + l], dx[l], s);
        t[j] = s;
    }

    const float* Pk = Phi + (size_t)k * NXD * NXD;
#pragma unroll
    for (int i = 0; i < NXD; i++) {
        float s = 0.f;
#pragma unroll
        for (int j = 0; j < NXD; j++)
            s = fmaf(Pk[i * NXD + j], t[j], s);
        g_f[(size_t)b * MD + k * NXD + i] = -2.0f * s;
    }
}

// ---------------------------------------------------------------------------
// Main persistent solver.
// SMEM: u_s[512][16] (u, [n][b] layout), f_s[512][16], Hs[2][8][512].
// Thread tile: 8 batch (as 4 f32x2 pairs) x 4 m.
// ---------------------------------------------------------------------------
__global__ __launch_bounds__(THREADS, 1)
void mpc_solve_kernel(const float* __restrict__ Hm, float* __restrict__ out) {
    extern __shared__ float sm[];
    float* u_s = sm;                    // [MD][BT]
    float* f_s = sm + MD * BT;          // [MD][BT]
    float* Hs  = sm + 2 * MD * BT;      // [2][NCH][MD]

    const int tid    = threadIdx.x;
    const int b_base = blockIdx.x * BT;
    const int m0     = (tid & 127) * 4; // 4 consecutive m per thread
    const int b0     = (tid >> 7) * 8;  // 8 batch rows per thread

    // Load f tile (transpose to [m][b]) and zero u.
    for (int i = tid; i < BT * MD; i += THREADS) {
        int b = i >> 9;           // / 512
        int m = i & (MD - 1);
        f_s[m * BT + b] = g_f[(size_t)(b_base + b) * MD + m];
        u_s[i] = 0.f;
    }
    __syncthreads();

    unsigned long long u_reg[4][4];     // [mi][b-pair], u0 = 0
#pragma unroll
    for (int mi = 0; mi < 4; mi++)
#pragma unroll
        for (int bp = 0; bp < 4; bp++)
            u_reg[mi][bp] = 0ull;

    for (int it = 0; it < ITERS; it++) {
        // acc = f
        unsigned long long acc[4][4];
#pragma unroll
        for (int mi = 0; mi < 4; mi++)
#pragma unroll
            for (int bp = 0; bp < 4; bp++)
                acc[mi][bp] =
                    *(const unsigned long long*)&f_s[(m0 + mi) * BT + b0 + 2 * bp];

        // Prime double-buffered H pipeline (chunks 0 and 1).
        for (int i = tid; i < NCH * MD / 4; i += THREADS)
            cp_async16(&Hs[0 * NCH * MD + i * 4], &Hm[0 * NCH * MD + i * 4]);
        cp_commit();
        for (int i = tid; i < NCH * MD / 4; i += THREADS)
            cp_async16(&Hs[1 * NCH * MD + i * 4], &Hm[1 * NCH * MD + i * 4]);
        cp_commit();

        for (int c = 0; c < NCHUNK; c++) {
            if (c == NCHUNK - 1) cp_wait<0>(); else cp_wait<1>();
            __syncthreads();

            const float* hb = &Hs[(c & 1) * NCH * MD];
            const int nbase = c * NCH;
#pragma unroll
            for (int np = 0; np < NCH; np++) {
                const int n = nbase + np;
                unsigned long long u2[4];
#pragma unroll
                for (int bp = 0; bp < 4; bp++)
                    u2[bp] = *(const unsigned long long*)&u_s[n * BT + b0 + 2 * bp];
                float4 h4 = *(const float4*)&hb[np * MD + m0];
                unsigned long long hh0 = pack2(h4.x, h4.x);
                unsigned long long hh1 = pack2(h4.y, h4.y);
                unsigned long long hh2 = pack2(h4.z, h4.z);
                unsigned long long hh3 = pack2(h4.w, h4.w);
#pragma unroll
                for (int bp = 0; bp < 4; bp++) {
                    fma2(acc[0][bp], u2[bp], hh0);
                    fma2(acc[1][bp], u2[bp], hh1);
                    fma2(acc[2][bp], u2[bp], hh2);
                    fma2(acc[3][bp], u2[bp], hh3);
                }
            }
            __syncthreads();   // all warps done reading buf[c&1]
            if (c + 2 < NCHUNK) {
                for (int i = tid; i < NCH * MD / 4; i += THREADS)
                    cp_async16(&Hs[(c & 1) * NCH * MD + i * 4],
                               &Hm[(size_t)(c + 2) * NCH * MD + i * 4]);
                cp_commit();
            }
        }

        // u <- clip(u - step * acc); write back to SMEM for next iteration.
#pragma unroll
        for (int mi = 0; mi < 4; mi++)
#pragma unroll
            for (int bp = 0; bp < 4; bp++) {
                float g0, g1, v0, v1;
                unpack2(acc[mi][bp], g0, g1);
                unpack2(u_reg[mi][bp], v0, v1);
                v0 = fminf(fmaxf(fmaf(-STEPC, g0, v0), -1.0f), 1.0f);
                v1 = fminf(fmaxf(fmaf(-STEPC, g1, v1), -1.0f), 1.0f);
                unsigned long long nv = pack2(v0, v1);
                u_reg[mi][bp] = nv;
                *(unsigned long long*)&u_s[(m0 + mi) * BT + b0 + 2 * bp] = nv;
            }
        __syncthreads();       // u_s consistent before next iteration's reads
    }

    // Epilogue: coalesced float4 stores, out[b][m].
#pragma unroll
    for (int j = 0; j < 8; j++) {
        int b  = b0 + j;
        int bp = j >> 1;
        int h  = j & 1;
        float vals[4];
#pragma unroll
        for (int mi = 0; mi < 4; mi++) {
            float lo, hi;
            unpack2(u_reg[mi][bp], lo, hi);
            vals[mi] = h ? hi : lo;
        }
        float4 v = make_float4(vals[0], vals[1], vals[2], vals[3]);
        *(float4*)&out[(size_t)(b_base + b) * MD + m0] = v;
    }
}

// ---------------------------------------------------------------------------
extern "C" void kernel_launch(void* const* d_in, const int* in_sizes, int n_in,
                              void* d_out, int out_size) {
    // metadata order: x0, xref, H, Phi, Q
    const float* xref = (const float*)d_in[1];
    const float* H    = (const float*)d_in[2];
    const float* Phi  = (const float*)d_in[3];
    const float* Q    = (const float*)d_in[4];
    float* out        = (float*)d_out;

    const int smem_bytes = (2 * MD * BT + 2 * NCH * MD) * (int)sizeof(float); // 96 KB
    cudaFuncSetAttribute(mpc_solve_kernel,
                         cudaFuncAttributeMaxDynamicSharedMemorySize, smem_bytes);

    mpc_f_kernel<<<BATCH, NHOR>>>(xref, Phi, Q);
    mpc_solve_kernel<<<BATCH / BT, THREADS, smem_bytes>>>(H, out);
}

// round 2
// speedup vs baseline: 1.1253x; 1.1253x over previous
#include <cuda_runtime.h>
#include <cuda_bf16.h>
#include <cstdint>

// ---------------------------------------------------------------------------
// LinearMPC: u <- clip(u - 0.01*(u@H^T + f)), 100 iters, B=2048, M=512.
// H symmetric => u@H^T = u@H (row-contiguous reduction).
// Persistent kernel, 512 threads/CTA (4 warps/SMSP), packed f32x2 FMA,
// 3-buffer cp.async H pipeline continuous across iterations.
// ---------------------------------------------------------------------------

#define NXD 8
#define NHOR 64
#define MD 512
#define BATCH 2048
#define BT 16            // batch rows per CTA
#define UST 20           // padded row stride for u_s / f_s (floats)
#define NCH 16           // H rows per chunk
#define NBUF 3
#define NCHUNK (MD / NCH)      // 32
#define ITERS 100
#define TOTCH (ITERS * NCHUNK) // 3200
#define STEPC 0.01f
#define THREADS 512

__device__ float g_f[BATCH * MD];

typedef unsigned long long u64;

// ---- packed f32x2 helpers (Blackwell FFMA2) -------------------------------
__device__ __forceinline__ u64 pack2(float lo, float hi) {
    u64 r;
    asm("mov.b64 %0, {%1, %2};" : "=l"(r) : "f"(lo), "f"(hi));
    return r;
}
__device__ __forceinline__ void unpack2(u64 v, float& lo, float& hi) {
    asm("mov.b64 {%0, %1}, %2;" : "=f"(lo), "=f"(hi) : "l"(v));
}
__device__ __forceinline__ void fma2(u64& d, u64 a, u64 b) {
    asm("fma.rn.f32x2 %0, %1, %2, %0;" : "+l"(d) : "l"(a), "l"(b));
}

// ---- cp.async helpers -----------------------------------------------------
__device__ __forceinline__ void cp_async16(void* smem, const void* gmem) {
    unsigned saddr = (unsigned)__cvta_generic_to_shared(smem);
    asm volatile("cp.async.cg.shared.global [%0], [%1], 16;" :: "r"(saddr), "l"(gmem));
}
__device__ __forceinline__ void cp_commit() {
    asm volatile("cp.async.commit_group;");
}
template <int N>
__device__ __forceinline__ void cp_wait() {
    asm volatile("cp.async.wait_group %0;" :: "n"(N));
}

__device__ __forceinline__ void prefetch_chunk(float* Hs, const float* Hm,
                                               int tid, int g) {
    const float* src = Hm + (size_t)(g & (NCHUNK - 1)) * NCH * MD;
    float* dst = Hs + (size_t)(g % NBUF) * NCH * MD;
#pragma unroll
    for (int r = 0; r < (NCH * MD / 4) / THREADS; r++) {
        int i = tid + r * THREADS;
        cp_async16(dst + i * 4, src + i * 4);
    }
    cp_commit();
}

// ---------------------------------------------------------------------------
// Prologue: f[b, k*8+i] = -2 * Phi[k] @ Q @ (xref[b,k] - xref[b,0])
// ---------------------------------------------------------------------------
__global__ void mpc_f_kernel(const float* __restrict__ xref,
                             const float* __restrict__ Phi,
                             const float* __restrict__ Q) {
    int b = blockIdx.x;
    int k = threadIdx.x;            // 0..63
    const float* xr = xref + (size_t)b * (NHOR + 1) * NXD;

    float dx[NXD];
#pragma unroll
    for (int l = 0; l < NXD; l++)
        dx[l] = xr[k * NXD + l] - xr[l];

    float t[NXD];
#pragma unroll
    for (int j = 0; j < NXD; j++) {
        float s = 0.f;
#pragma unroll
        for (int l = 0; l < NXD; l++)
            s = fmaf(Q[j * NXD + l], dx[l], s);
        t[j] = s;
    }

    const float* Pk = Phi + (size_t)k * NXD * NXD;
#pragma unroll
    for (int i = 0; i < NXD; i++) {
        float s = 0.f;
#pragma unroll
        for (int j = 0; j < NXD; j++)
            s = fmaf(Pk[i * NXD + j], t[j], s);
        g_f[(size_t)b * MD + k * NXD + i] = -2.0f * s;
    }
}

// ---------------------------------------------------------------------------
// Main persistent solver.
// SMEM: u_s[512][20], f_s[512][20]  ([m][b] layout, padded stride)
//       Hs[3][16][512]              (H row chunks, 3-deep cp.async ring)
// Thread tile: 2 m  x  8 batch (4 f32x2 pairs along batch).
// ---------------------------------------------------------------------------
__global__ __launch_bounds__(THREADS, 1)
void mpc_solve_kernel(const float* __restrict__ Hm, float* __restrict__ out) {
    extern __shared__ float sm[];
    float* u_s = sm;                       // [MD][UST]
    float* f_s = sm + MD * UST;            // [MD][UST]
    float* Hs  = sm + 2 * MD * UST;        // [NBUF][NCH][MD]

    const int tid    = threadIdx.x;
    const int b_base = blockIdx.x * BT;
    const int m0     = (tid & 255) * 2;    // 2 consecutive m
    const int b0     = (tid >> 8) * 8;     // 8 batch rows (4 pairs)

    // Load f tile into [m][b] layout; zero u.
    for (int i = tid; i < BT * MD; i += THREADS) {
        int b = i >> 9;               // / 512
        int m = i & (MD - 1);
        f_s[m * UST + b] = g_f[(size_t)(b_base + b) * MD + m];
        u_s[m * UST + b] = 0.f;
    }
    __syncthreads();

    u64 u_reg[2][4];
#pragma unroll
    for (int mi = 0; mi < 2; mi++)
#pragma unroll
        for (int bp = 0; bp < 4; bp++)
            u_reg[mi][bp] = 0ull;

    // acc = f
    u64 acc[2][4];
#pragma unroll
    for (int mi = 0; mi < 2; mi++) {
        ulonglong2 fa = *(const ulonglong2*)&f_s[(m0 + mi) * UST + b0];
        ulonglong2 fb = *(const ulonglong2*)&f_s[(m0 + mi) * UST + b0 + 4];
        acc[mi][0] = fa.x; acc[mi][1] = fa.y;
        acc[mi][2] = fb.x; acc[mi][3] = fb.y;
    }

    // Prime the 3-buffer pipeline.
    prefetch_chunk(Hs, Hm, tid, 0);
    prefetch_chunk(Hs, Hm, tid, 1);

    for (int g = 0; g < TOTCH; g++) {
        if (g == TOTCH - 1) cp_wait<0>(); else cp_wait<1>();
        __syncthreads();   // buffer g%3 complete+visible; u_s writes visible

        const float* hb = Hs + (size_t)(g % NBUF) * NCH * MD;
        const int c = g & (NCHUNK - 1);
        const float* ubase = &u_s[(size_t)c * NCH * UST + b0];

#pragma unroll
        for (int np = 0; np < NCH; np++) {
            ulonglong2 ua = *(const ulonglong2*)(ubase + np * UST);
            ulonglong2 ub = *(const ulonglong2*)(ubase + np * UST + 4);
            float2 h2 = *(const float2*)&hb[np * MD + m0];
            u64 hh0 = pack2(h2.x, h2.x);
            u64 hh1 = pack2(h2.y, h2.y);
            fma2(acc[0][0], ua.x, hh0);
            fma2(acc[0][1], ua.y, hh0);
            fma2(acc[0][2], ub.x, hh0);
            fma2(acc[0][3], ub.y, hh0);
            fma2(acc[1][0], ua.x, hh1);
            fma2(acc[1][1], ua.y, hh1);
            fma2(acc[1][2], ub.x, hh1);
            fma2(acc[1][3], ub.y, hh1);
        }

        // Keep the H stream rolling (crosses iteration boundaries; H reused).
        if (g + 2 < TOTCH) prefetch_chunk(Hs, Hm, tid, g + 2);

        if (c == NCHUNK - 1) {
            __syncthreads();   // everyone done reading u_s this iteration
            // u <- clip(u - step*acc); write back; acc <- f for next iter.
#pragma unroll
            for (int mi = 0; mi < 2; mi++)
#pragma unroll
                for (int bp = 0; bp < 4; bp++) {
                    float g0, g1, v0, v1;
                    unpack2(acc[mi][bp], g0, g1);
                    unpack2(u_reg[mi][bp], v0, v1);
                    v0 = fminf(fmaxf(fmaf(-STEPC, g0, v0), -1.0f), 1.0f);
                    v1 = fminf(fmaxf(fmaf(-STEPC, g1, v1), -1.0f), 1.0f);
                    u64 nv = pack2(v0, v1);
                    u_reg[mi][bp] = nv;
                    *(u64*)&u_s[(m0 + mi) * UST + b0 + 2 * bp] = nv;
                }
            if (g != TOTCH - 1) {
#pragma unroll
                for (int mi = 0; mi < 2; mi++) {
                    ulonglong2 fa = *(const ulonglong2*)&f_s[(m0 + mi) * UST + b0];
                    ulonglong2 fb = *(const ulonglong2*)&f_s[(m0 + mi) * UST + b0 + 4];
                    acc[mi][0] = fa.x; acc[mi][1] = fa.y;
                    acc[mi][2] = fb.x; acc[mi][3] = fb.y;
                }
            }
            // next loop-top __syncthreads orders these writes before reads
        }
    }

    // Epilogue: out[b][m], 8 batch x 2 m per thread, coalesced STG.64.
#pragma unroll
    for (int bp = 0; bp < 4; bp++) {
        float v0, v1, w0, w1;
        unpack2(u_reg[0][bp], v0, v1);   // m0   : batches (2bp, 2bp+1)
        unpack2(u_reg[1][bp], w0, w1);   // m0+1 : batches (2bp, 2bp+1)
#pragma unroll
        for (int h = 0; h < 2; h++) {
            int b = b_base + b0 + 2 * bp + h;
            float2 o;
            o.x = h ? v1 : v0;
            o.y = h ? w1 : w0;
            *(float2*)&out[(size_t)b * MD + m0] = o;
        }
    }
}

// ---------------------------------------------------------------------------
extern "C" void kernel_launch(void* const* d_in, const int* in_sizes, int n_in,
                              void* d_out, int out_size) {
    // metadata order: x0, xref, H, Phi, Q
    const float* xref = (const float*)d_in[1];
    const float* H    = (const float*)d_in[2];
    const float* Phi  = (const float*)d_in[3];
    const float* Q    = (const float*)d_in[4];
    float* out        = (float*)d_out;

    const int smem_bytes = (2 * MD * UST + NBUF * NCH * MD) * (int)sizeof(float);
    cudaFuncSetAttribute(mpc_solve_kernel,
                         cudaFuncAttributeMaxDynamicSharedMemorySize, smem_bytes);

    mpc_f_kernel<<<BATCH, NHOR>>>(xref, Phi, Q);
    mpc_solve_kernel<<<BATCH / BT, THREADS, smem_bytes>>>(H, out);
}

// round 3
// speedup vs baseline: 1.3725x; 1.2197x over previous
#include <cuda_runtime.h>
#include <cuda_bf16.h>
#include <cstdint>

// ---------------------------------------------------------------------------
// LinearMPC: u <- clip(u - 0.01*(u@H^T + f)), 100 iters, B=2048, M=512.
// H symmetric => u@H^T = u@H (row-contiguous reduction).
// R3: H is L2-resident; stream it straight to registers with __ldg (no SMEM
// staging, no cp.async, no per-chunk barriers). u,f live in SMEM [m][b].
// Register double-buffered 8-row H pipeline; 2 block barriers per iteration.
// ---------------------------------------------------------------------------

#define NXD 8
#define NHOR 64
#define MD 512
#define BATCH 2048
#define BT 16            // batch rows per CTA
#define UST 20           // padded row stride for u_s / f_s (floats)
#define NG 8             // H rows per register group
#define NGRP (MD / NG)   // 64
#define ITERS 100
#define STEPC 0.01f
#define THREADS 512

__device__ float g_f[BATCH * MD];

typedef unsigned long long u64;

// ---- packed f32x2 helpers (Blackwell FFMA2) -------------------------------
__device__ __forceinline__ u64 pack2(float lo, float hi) {
    u64 r;
    asm("mov.b64 %0, {%1, %2};" : "=l"(r) : "f"(lo), "f"(hi));
    return r;
}
__device__ __forceinline__ void unpack2(u64 v, float& lo, float& hi) {
    asm("mov.b64 {%0, %1}, %2;" : "=f"(lo), "=f"(hi) : "l"(v));
}
__device__ __forceinline__ void fma2(u64& d, u64 a, u64 b) {
    asm("fma.rn.f32x2 %0, %1, %2, %0;" : "+l"(d) : "l"(a), "l"(b));
}

// ---------------------------------------------------------------------------
// Prologue: f[b, k*8+i] = -2 * Phi[k] @ Q @ (xref[b,k] - xref[b,0])
// ---------------------------------------------------------------------------
__global__ void mpc_f_kernel(const float* __restrict__ xref,
                             const float* __restrict__ Phi,
                             const float* __restrict__ Q) {
    int b = blockIdx.x;
    int k = threadIdx.x;            // 0..63
    const float* xr = xref + (size_t)b * (NHOR + 1) * NXD;

    float dx[NXD];
#pragma unroll
    for (int l = 0; l < NXD; l++)
        dx[l] = xr[k * NXD + l] - xr[l];

    float t[NXD];
#pragma unroll
    for (int j = 0; j < NXD; j++) {
        float s = 0.f;
#pragma unroll
        for (int l = 0; l < NXD; l++)
            s = fmaf(Q[j * NXD + l], dx[l], s);
        t[j] = s;
    }

    const float* Pk = Phi + (size_t)k * NXD * NXD;
#pragma unroll
    for (int i = 0; i < NXD; i++) {
        float s = 0.f;
#pragma unroll
        for (int j = 0; j < NXD; j++)
            s = fmaf(Pk[i * NXD + j], t[j], s);
        g_f[(size_t)b * MD + k * NXD + i] = -2.0f * s;
    }
}

// ---------------------------------------------------------------------------
// Main persistent solver. Thread tile: 2 m x 8 batch (4 f32x2 pairs on b).
// ---------------------------------------------------------------------------
__global__ __launch_bounds__(THREADS, 1)
void mpc_solve_kernel(const float* __restrict__ Hm, float* __restrict__ out) {
    extern __shared__ float sm[];
    float* u_s = sm;                       // [MD][UST]
    float* f_s = sm + MD * UST;            // [MD][UST]

    const int tid    = threadIdx.x;
    const int b_base = blockIdx.x * BT;
    const int m0     = (tid & 255) * 2;    // 2 consecutive m
    const int b0     = (tid >> 8) * 8;     // 8 batch rows (4 pairs)

    // Load f tile into [m][b] layout; zero u.
    for (int i = tid; i < BT * MD; i += THREADS) {
        int b = i >> 9;               // / 512
        int m = i & (MD - 1);
        f_s[m * UST + b] = g_f[(size_t)(b_base + b) * MD + m];
        u_s[m * UST + b] = 0.f;
    }

    u64 u_reg[2][4];
#pragma unroll
    for (int mi = 0; mi < 2; mi++)
#pragma unroll
        for (int bp = 0; bp < 4; bp++)
            u_reg[mi][bp] = 0ull;

    const float2* __restrict__ Hp =
        (const float2*)(Hm + m0);          // row n: Hp[n * (MD/2)]

    __syncthreads();

    for (int it = 0; it < ITERS; it++) {
        // acc = f
        u64 acc[2][4];
#pragma unroll
        for (int mi = 0; mi < 2; mi++) {
            ulonglong2 fa = *(const ulonglong2*)&f_s[(m0 + mi) * UST + b0];
            ulonglong2 fb = *(const ulonglong2*)&f_s[(m0 + mi) * UST + b0 + 4];
            acc[mi][0] = fa.x; acc[mi][1] = fa.y;
            acc[mi][2] = fb.x; acc[mi][3] = fb.y;
        }

        float2 hA[NG], hB[NG];

        // Prime: group 0 -> hA
#pragma unroll
        for (int j = 0; j < NG; j++)
            hA[j] = __ldg(&Hp[(size_t)j * (MD / 2)]);

#define COMPUTE_GROUP(HCUR, HNXT, GIDX)                                       \
        {                                                                     \
            const int gn = ((GIDX) + 1 < NGRP) ? (GIDX) + 1 : (GIDX);         \
            _Pragma("unroll")                                                 \
            for (int j = 0; j < NG; j++)                                      \
                HNXT[j] = __ldg(&Hp[(size_t)(gn * NG + j) * (MD / 2)]);       \
            _Pragma("unroll")                                                 \
            for (int j = 0; j < NG; j++) {                                    \
                const int n = (GIDX) * NG + j;                                \
                ulonglong2 ua = *(const ulonglong2*)&u_s[n * UST + b0];       \
                ulonglong2 ub = *(const ulonglong2*)&u_s[n * UST + b0 + 4];   \
                u64 hh0 = pack2(HCUR[j].x, HCUR[j].x);                        \
                u64 hh1 = pack2(HCUR[j].y, HCUR[j].y);                        \
                fma2(acc[0][0], ua.x, hh0);                                   \
                fma2(acc[0][1], ua.y, hh0);                                   \
                fma2(acc[0][2], ub.x, hh0);                                   \
                fma2(acc[0][3], ub.y, hh0);                                   \
                fma2(acc[1][0], ua.x, hh1);                                   \
                fma2(acc[1][1], ua.y, hh1);                                   \
                fma2(acc[1][2], ub.x, hh1);                                   \
                fma2(acc[1][3], ub.y, hh1);                                   \
            }                                                                 \
        }

#pragma unroll 1
        for (int ng = 0; ng < NGRP; ng += 2) {
            COMPUTE_GROUP(hA, hB, ng);
            COMPUTE_GROUP(hB, hA, ng + 1);
        }
#undef COMPUTE_GROUP

        __syncthreads();   // all warps done reading u_s this iteration

        // u <- clip(u - step*acc); write back to SMEM.
#pragma unroll
        for (int mi = 0; mi < 2; mi++)
#pragma unroll
            for (int bp = 0; bp < 4; bp++) {
                float g0, g1, v0, v1;
                unpack2(acc[mi][bp], g0, g1);
                unpack2(u_reg[mi][bp], v0, v1);
                v0 = fminf(fmaxf(fmaf(-STEPC, g0, v0), -1.0f), 1.0f);
                v1 = fminf(fmaxf(fmaf(-STEPC, g1, v1), -1.0f), 1.0f);
                u64 nv = pack2(v0, v1);
                u_reg[mi][bp] = nv;
                *(u64*)&u_s[(m0 + mi) * UST + b0 + 2 * bp] = nv;
            }

        __syncthreads();   // u_s consistent before next iteration's reads
    }

    // Epilogue: out[b][m], 8 batch x 2 m per thread, coalesced STG.64.
#pragma unroll
    for (int bp = 0; bp < 4; bp++) {
        float v0, v1, w0, w1;
        unpack2(u_reg[0][bp], v0, v1);   // m0   : batches (2bp, 2bp+1)
        unpack2(u_reg[1][bp], w0, w1);   // m0+1 : batches (2bp, 2bp+1)
#pragma unroll
        for (int h = 0; h < 2; h++) {
            int b = b_base + b0 + 2 * bp + h;
            float2 o;
            o.x = h ? v1 : v0;
            o.y = h ? w1 : w0;
            *(float2*)&out[(size_t)b * MD + m0] = o;
        }
    }
}

// ---------------------------------------------------------------------------
extern "C" void kernel_launch(void* const* d_in, const int* in_sizes, int n_in,
                              void* d_out, int out_size) {
    // metadata order: x0, xref, H, Phi, Q
    const float* xref = (const float*)d_in[1];
    const float* H    = (const float*)d_in[2];
    const float* Phi  = (const float*)d_in[3];
    const float* Q    = (const float*)d_in[4];
    float* out        = (float*)d_out;

    const int smem_bytes = (2 * MD * UST) * (int)sizeof(float);   // 80 KB
    cudaFuncSetAttribute(mpc_solve_kernel,
                         cudaFuncAttributeMaxDynamicSharedMemorySize, smem_bytes);

    mpc_f_kernel<<<BATCH, NHOR>>>(xref, Phi, Q);
    mpc_solve_kernel<<<BATCH / BT, THREADS, smem_bytes>>>(H, out);
}